// round 6
// baseline (speedup 1.0000x reference)
#include <cuda_runtime.h>
#include <cuda_bf16.h>
#include <cstdint>

// Only Z0[:,:,-1] = conv(X0, t=10) is nonzero.  Softmax degree-norm is a no-op.
// Single persistent kernel, 6 phases, 5 grid barriers.

#define NBLK 148
#define NTHR 256
#define NT (NBLK * NTHR)

// ---------------- device scratch ----------------
__device__ float g_obs2[2 * 8192];     // MLP input rows t=9,10
__device__ float g_s1[2 * 2048];       // accum (no bias), zeroed in P5
__device__ float g_s2[2 * 2048];       // accum, zeroed in P5
__device__ float g_s3[2 * 12288];      // accum; row0=X9, row1=X10 (pre-bias/relu)
__device__ float g_sph[12 * 256];      // accum (no bias), zeroed in P5
__device__ float g_tph[256];           // plain store (pre-bias)
__device__ float g_U[3 * 1024 * 12];   // [c][n][tau], c = feat-9
__device__ float g_Y[1024 * 12];
__device__ float g_E[3 * 1024 * 1024]; // exp weights
__device__ float g_rs[3 * 1024];       // row sums
__device__ float g_G[3 * 1024 * 12];   // normalized A@X rows

// ---------------- grid barrier (sense-reversing, replay-safe) --------------
__device__ unsigned g_bar_cnt[8];
__device__ unsigned g_bar_flag[8];

__device__ __forceinline__ void grid_barrier(int i) {
    __syncthreads();
    if (threadIdx.x == 0) {
        volatile unsigned* fl = &g_bar_flag[i];
        unsigned sense = *fl;
        __threadfence();
        unsigned old = atomicAdd(&g_bar_cnt[i], 1);
        if (old == NBLK - 1) {
            g_bar_cnt[i] = 0;
            __threadfence();
            *fl = sense ^ 1u;
        } else {
            while (*fl == sense) { }
        }
        __threadfence();
    }
    __syncthreads();
}

// ---------------- gemv tile: M=2 rows, 4 cols, LEN-k chunk -----------------
template<int K, int N, int LEN, bool RELU>
__device__ __forceinline__ void gemv_tile(const float* __restrict__ A,
                                          const float* __restrict__ bias,
                                          const float* __restrict__ W,
                                          float* __restrict__ S,
                                          int col, int k0) {
    float a00 = 0, a01 = 0, a02 = 0, a03 = 0;
    float a10 = 0, a11 = 0, a12 = 0, a13 = 0;
#pragma unroll 8
    for (int k = k0; k < k0 + LEN; ++k) {
        const float4 w = *reinterpret_cast<const float4*>(W + (size_t)k * N + col);
        float x0 = A[k], x1 = A[K + k];
        if (RELU) {
            float bb = bias[k];
            x0 = fmaxf(x0 + bb, 0.0f); x1 = fmaxf(x1 + bb, 0.0f);
        }
        a00 += x0 * w.x; a01 += x0 * w.y; a02 += x0 * w.z; a03 += x0 * w.w;
        a10 += x1 * w.x; a11 += x1 * w.y; a12 += x1 * w.z; a13 += x1 * w.w;
    }
    atomicAdd(S + col + 0, a00); atomicAdd(S + col + 1, a01);
    atomicAdd(S + col + 2, a02); atomicAdd(S + col + 3, a03);
    atomicAdd(S + N + col + 0, a10); atomicAdd(S + N + col + 1, a11);
    atomicAdd(S + N + col + 2, a12); atomicAdd(S + N + col + 3, a13);
}

// ---------------- the single mega kernel ----------------
__global__ void __launch_bounds__(NTHR, 1)
mega2_kernel(const float* __restrict__ obs,
             const float* __restrict__ tf,
             const float* __restrict__ fc_w1, const float* __restrict__ b1,
             const float* __restrict__ fc_w2, const float* __restrict__ b2,
             const float* __restrict__ fc_w3, const float* __restrict__ b3,
             const float* __restrict__ Wf, const float* __restrict__ Wb,
             const float* __restrict__ bvec,
             const float* __restrict__ li,
             const float* __restrict__ gs_w1, const float* __restrict__ gs_b1,
             const float* __restrict__ gs_w2, const float* __restrict__ gs_b2,
             const float* __restrict__ gt_w1, const float* __restrict__ gt_b1,
             const float* __restrict__ gt_w2, const float* __restrict__ gt_b2,
             const float* __restrict__ Bm,
             float* __restrict__ out) {
    const int tid = threadIdx.x, bid = blockIdx.x;
    const int gt = bid * NTHR + tid;
    const int lane = tid & 31;

    // ======== P0: obs gather, out-tail zero, sph split-K (coalesced), tph ==
    for (int i = gt; i < 16384 + 36864; i += NT) {
        if (i < 16384) {
            int m = i >> 13, k = i & 8191;
            int n = k >> 3, d = k & 7;
            g_obs2[i] = obs[n * 96 + d * 12 + 9 + m];
        } else {
            out[12288 + (i - 16384)] = 0.0f;
        }
    }
    if (gt < 24576) {                       // sph: 12 tau x 8 kc x 256 t
        int t = gt & 255;
        int rr = gt >> 8;                   // 0..95
        int tau = rr / 8, kc = rr & 7;
        const float* lr = li + tau * 1024 + kc * 128;
        const float* w  = gs_w1 + (size_t)(kc * 128) * 256 + t;
        float acc = 0.0f;
#pragma unroll 16
        for (int k = 0; k < 128; ++k) acc += lr[k] * w[(size_t)k * 256];
        atomicAdd(&g_sph[tau * 256 + t], acc);
    } else if (gt < 24832) {                // tph
        int t = gt - 24576;
        float acc = 0.0f;
#pragma unroll
        for (int k = 0; k < 36; ++k) acc += tf[k] * gt_w1[k * 256 + t];
        g_tph[t] = acc;                     // bias at read
    }
    grid_barrier(0);

    // ======== P1: u+y (blocks 0..55)  ||  gemv1 (blocks 56..147) ===========
    if (bid < 56) {
        int lw = bid * 8 + (tid >> 5);      // 0..447
        for (int task = lw; task < 3072; task += 448) {
            int n = task / 3, c = task - n * 3;
            int j = n * 12 + 9 + c;
            float wg[8], wt[8], bg[8];
#pragma unroll
            for (int i = 0; i < 8; ++i) {
                int k = lane + 32 * i;
                wg[i] = gs_w2[(size_t)k * 12288 + j];
                wt[i] = gt_w2[(size_t)k * 12288 + j];
                bg[i] = gs_b1[k];
            }
            float tp = 0.0f;
#pragma unroll
            for (int i = 0; i < 8; ++i) {
                int k = lane + 32 * i;
                tp += fmaxf(g_tph[k] + gt_b1[k], 0.0f) * wt[i];
            }
#pragma unroll
            for (int o = 16; o; o >>= 1) tp += __shfl_xor_sync(0xffffffffu, tp, o);
            float tpv = fmaxf(tp + gt_b2[j], 0.0f);
            float bsp = gs_b2[j];

            float bm[12];
            bool doy = (c == 1);
            if (doy && lane < 12) {
#pragma unroll
                for (int q = 0; q < 12; ++q) bm[q] = Bm[lane * 12 + q];
            } else {
#pragma unroll
                for (int q = 0; q < 12; ++q) bm[q] = 0.0f;
            }
            float yacc = 0.0f;
#pragma unroll
            for (int tau = 0; tau < 12; ++tau) {
                float sp = 0.0f;
#pragma unroll
                for (int i = 0; i < 8; ++i)
                    sp += fmaxf(g_sph[tau * 256 + lane + 32 * i] + bg[i], 0.0f) * wg[i];
#pragma unroll
                for (int o = 16; o; o >>= 1) sp += __shfl_xor_sync(0xffffffffu, sp, o);
                float v = fmaxf(sp + bsp, 0.0f) + tpv;
                if (lane == tau) g_U[c * 12288 + n * 12 + tau] = v;
                yacc += bm[tau] * v;
            }
            if (doy && lane < 12) g_Y[n * 12 + lane] = yacc;
        }
    } else {
        int lt = (bid - 56) * NTHR + tid;
        for (int tile = lt; tile < 512 * 64; tile += 92 * NTHR) {
            int col4 = tile & 511, kc = tile >> 9;
            gemv_tile<8192, 2048, 128, false>(g_obs2, b1, fc_w1, g_s1,
                                              col4 * 4, kc * 128);
        }
    }
    grid_barrier(1);

    // ======== P2: exp matrix (blocks 0..47)  ||  gemv2 (48..147) ===========
    if (bid < 48) {
        int lw = bid * 8 + (tid >> 5);      // 0..383
        for (int task = lw; task < 3072; task += 384) {
            int ap = task >> 10, i = task & 1023;
            int cidx = (ap == 0) ? 1 : (ap == 1 ? 0 : 2);   // a = 10,9,11
            const float* Urow = g_U + cidx * 12288 + i * 12;
            float u[12];
#pragma unroll
            for (int q = 0; q < 12; ++q) u[q] = Urow[q];
            float* Erow = g_E + (size_t)task * 1024;
            float rs = 0.0f;
            for (int j = lane; j < 1024; j += 32) {
                const float4* yr = (const float4*)(g_Y + j * 12);
                float4 ya = yr[0], yb = yr[1], yc = yr[2];
                float s = u[0]*ya.x + u[1]*ya.y + u[2] *ya.z + u[3] *ya.w
                        + u[4]*yb.x + u[5]*yb.y + u[6] *yb.z + u[7] *yb.w
                        + u[8]*yc.x + u[9]*yc.y + u[10]*yc.z + u[11]*yc.w;
                s = (s >= 0.05f) ? s : 0.0f;
                float e = __expf(s);
                Erow[j] = e;
                rs += e;
            }
#pragma unroll
            for (int o = 16; o; o >>= 1) rs += __shfl_xor_sync(0xffffffffu, rs, o);
            if (lane == 0) g_rs[task] = rs;
        }
    } else {
        int lt = (bid - 48) * NTHR + tid;
        for (int tile = lt; tile < 512 * 64; tile += 100 * NTHR) {
            int col4 = tile & 511, kc = tile >> 9;
            gemv_tile<2048, 2048, 32, true>(g_s1, b1, fc_w2, g_s2,
                                            col4 * 4, kc * 32);
        }
    }
    grid_barrier(2);

    // ======== P3: gemv3 (all blocks) ========================================
    for (int tile = gt; tile < 3072 * 16; tile += NT) {
        int col4 = tile % 3072, kc = tile / 3072;
        gemv_tile<2048, 12288, 128, true>(g_s2, b2, fc_w3, g_s3,
                                          col4 * 4, kc * 128);
    }
    grid_barrier(3);

    // ======== P4: SpMM  G[ap][i] = (E[ap][i] @ relu(X+b)) / rs =============
    {
        int lw = gt >> 5;                   // 0..1183
        for (int task = lw; task < 3072; task += (NT >> 5)) {
            int ap = task >> 10;
            const float* Erow = g_E + (size_t)task * 1024;
            const float* X = g_s3 + (ap == 0 ? 12288 : 0);
            float g[12];
#pragma unroll
            for (int q = 0; q < 12; ++q) g[q] = 0.0f;
            for (int j = lane; j < 1024; j += 32) {
                float e = Erow[j];
                const float4* xr = (const float4*)(X + j * 12);
                const float4* br = (const float4*)(b3 + j * 12);
                float4 xa = xr[0], xb = xr[1], xc = xr[2];
                float4 ba = br[0], bb = br[1], bc = br[2];
                g[0] += e * fmaxf(xa.x + ba.x, 0.0f);
                g[1] += e * fmaxf(xa.y + ba.y, 0.0f);
                g[2] += e * fmaxf(xa.z + ba.z, 0.0f);
                g[3] += e * fmaxf(xa.w + ba.w, 0.0f);
                g[4] += e * fmaxf(xb.x + bb.x, 0.0f);
                g[5] += e * fmaxf(xb.y + bb.y, 0.0f);
                g[6] += e * fmaxf(xb.z + bb.z, 0.0f);
                g[7] += e * fmaxf(xb.w + bb.w, 0.0f);
                g[8] += e * fmaxf(xc.x + bc.x, 0.0f);
                g[9] += e * fmaxf(xc.y + bc.y, 0.0f);
                g[10]+= e * fmaxf(xc.z + bc.z, 0.0f);
                g[11]+= e * fmaxf(xc.w + bc.w, 0.0f);
            }
#pragma unroll
            for (int q = 0; q < 12; ++q) {
#pragma unroll
                for (int o = 16; o; o >>= 1)
                    g[q] += __shfl_xor_sync(0xffffffffu, g[q], o);
            }
            if (lane == 0) {
                float inv = 1.0f / g_rs[task];
#pragma unroll
                for (int q = 0; q < 12; ++q) g_G[task * 12 + q] = g[q] * inv;
            }
        }
    }
    grid_barrier(4);

    // ======== P5: combine + zero accumulators ==============================
    for (int idx = gt; idx < 12288 + 35840; idx += NT) {
        if (idx < 12288) {
            int n = idx / 12, f = idx % 12;
            float acc1 = bvec[f], acc2 = bvec[f];
#pragma unroll
            for (int q = 0; q < 12; ++q) {
                acc1 += g_G[n * 12 + q] * (Wf[q * 12 + f] + Wb[q * 12 + f]);
                acc2 += g_G[(1024 + n) * 12 + q] * Wf[144 + q * 12 + f]
                      + g_G[(2048 + n) * 12 + q] * Wb[144 + q * 12 + f];
            }
            out[idx] = fmaxf(acc1, 0.0f) + fmaxf(acc2, 0.0f);
        } else {
            int i = idx - 12288;
            if (i < 4096)        g_s1[i] = 0.0f;
            else if (i < 8192)   g_s2[i - 4096] = 0.0f;
            else if (i < 32768)  g_s3[i - 8192] = 0.0f;
            else                 g_sph[i - 32768] = 0.0f;
        }
    }
}

// ---------------- launch ----------------
extern "C" void kernel_launch(void* const* d_in, const int* in_sizes, int n_in,
                              void* d_out, int out_size) {
    const float* obs    = (const float*)d_in[0];
    const float* tf     = (const float*)d_in[1];
    const float* fc_w1  = (const float*)d_in[2];
    const float* fc_b1  = (const float*)d_in[3];
    const float* fc_w2  = (const float*)d_in[4];
    const float* fc_b2  = (const float*)d_in[5];
    const float* fc_w3  = (const float*)d_in[6];
    const float* fc_b3  = (const float*)d_in[7];
    const float* Wf     = (const float*)d_in[8];
    const float* Wb     = (const float*)d_in[9];
    const float* bvec   = (const float*)d_in[10];
    const float* li     = (const float*)d_in[11];
    const float* gs_w1  = (const float*)d_in[12];
    const float* gs_b1  = (const float*)d_in[13];
    const float* gs_w2  = (const float*)d_in[14];
    const float* gs_b2  = (const float*)d_in[15];
    const float* gt_w1  = (const float*)d_in[16];
    const float* gt_b1  = (const float*)d_in[17];
    const float* gt_w2  = (const float*)d_in[18];
    const float* gt_b2  = (const float*)d_in[19];
    const float* Bm     = (const float*)d_in[20];
    float* out = (float*)d_out;

    mega2_kernel<<<NBLK, NTHR>>>(obs, tf, fc_w1, fc_b1, fc_w2, fc_b2,
                                 fc_w3, fc_b3, Wf, Wb, bvec, li,
                                 gs_w1, gs_b1, gs_w2, gs_b2,
                                 gt_w1, gt_b1, gt_w2, gt_b2, Bm, out);
}

// round 7
// speedup vs baseline: 1.6161x; 1.6161x over previous
#include <cuda_runtime.h>
#include <cuda_bf16.h>
#include <cstdint>

// Only Z0[:,:,-1] = conv(X0, t=10) is nonzero.  Softmax degree-norm is a no-op.
// Single persistent kernel, phases separated by replay-safe grid barriers.

#define NBLK 148
#define NTHR 512
#define NT (NBLK * NTHR)
#define NWARP (NBLK * (NTHR / 32))

// ---------------- device scratch ----------------
__device__ float g_obs2[2 * 8192];     // MLP input rows t=9,10
__device__ float g_s1[2 * 2048];       // accum (no bias), zeroed in P5
__device__ float g_s2[2 * 2048];       // accum, zeroed in P5
__device__ float g_s3[2 * 12288];      // accum; row0=X9, row1=X10 (pre-bias/relu)
__device__ float g_sph[12 * 256];      // accum (no bias), zeroed in P5
__device__ float g_tph[256];           // plain store (pre-bias)
__device__ float g_U[3 * 1024 * 12];   // [c][n][tau], c = feat-9
__device__ float g_Y[1024 * 12];
__device__ float g_G[3 * 1024 * 12];   // normalized (A@X) rows

// ---------------- grid barrier (sense-reversing, replay-safe) --------------
__device__ unsigned g_bar_cnt[8];
__device__ unsigned g_bar_flag[8];

__device__ __forceinline__ void grid_barrier(int i) {
    __syncthreads();
    if (threadIdx.x == 0) {
        volatile unsigned* fl = &g_bar_flag[i];
        unsigned sense = *fl;
        __threadfence();
        unsigned old = atomicAdd(&g_bar_cnt[i], 1);
        if (old == NBLK - 1) {
            g_bar_cnt[i] = 0;
            __threadfence();
            *fl = sense ^ 1u;
        } else {
            while (*fl == sense) { }
        }
        __threadfence();
    }
    __syncthreads();
}

// ---------------- gemv tile: M=2 rows, 4 cols, LEN-k chunk -----------------
template<int K, int N, int LEN, bool RELU>
__device__ __forceinline__ void gemv_tile(const float* __restrict__ A,
                                          const float* __restrict__ bias,
                                          const float* __restrict__ W,
                                          float* __restrict__ S,
                                          int col, int k0) {
    float a00 = 0, a01 = 0, a02 = 0, a03 = 0;
    float a10 = 0, a11 = 0, a12 = 0, a13 = 0;
#pragma unroll 8
    for (int k = k0; k < k0 + LEN; ++k) {
        const float4 w = *reinterpret_cast<const float4*>(W + (size_t)k * N + col);
        float x0 = A[k], x1 = A[K + k];
        if (RELU) {
            float bb = bias[k];
            x0 = fmaxf(x0 + bb, 0.0f); x1 = fmaxf(x1 + bb, 0.0f);
        }
        a00 += x0 * w.x; a01 += x0 * w.y; a02 += x0 * w.z; a03 += x0 * w.w;
        a10 += x1 * w.x; a11 += x1 * w.y; a12 += x1 * w.z; a13 += x1 * w.w;
    }
    atomicAdd(S + col + 0, a00); atomicAdd(S + col + 1, a01);
    atomicAdd(S + col + 2, a02); atomicAdd(S + col + 3, a03);
    atomicAdd(S + N + col + 0, a10); atomicAdd(S + N + col + 1, a11);
    atomicAdd(S + N + col + 2, a12); atomicAdd(S + N + col + 3, a13);
}

#define SMEM_FLOATS (3 * 12288)

__device__ __forceinline__ float4 relu4b(float4 v, float4 b) {
    v.x = fmaxf(v.x + b.x, 0.0f); v.y = fmaxf(v.y + b.y, 0.0f);
    v.z = fmaxf(v.z + b.z, 0.0f); v.w = fmaxf(v.w + b.w, 0.0f);
    return v;
}

// ---------------- the single mega kernel ----------------
__global__ void __launch_bounds__(NTHR, 1)
mega3_kernel(const float* __restrict__ obs,
             const float* __restrict__ tf,
             const float* __restrict__ fc_w1, const float* __restrict__ b1,
             const float* __restrict__ fc_w2, const float* __restrict__ b2,
             const float* __restrict__ fc_w3, const float* __restrict__ b3,
             const float* __restrict__ Wf, const float* __restrict__ Wb,
             const float* __restrict__ bvec,
             const float* __restrict__ li,
             const float* __restrict__ gs_w1, const float* __restrict__ gs_b1,
             const float* __restrict__ gs_w2, const float* __restrict__ gs_b2,
             const float* __restrict__ gt_w1, const float* __restrict__ gt_b1,
             const float* __restrict__ gt_w2, const float* __restrict__ gt_b2,
             const float* __restrict__ Bm,
             float* __restrict__ out) {
    extern __shared__ float sm[];
    float* sY   = sm;
    float* sX10 = sm + 12288;
    float* sX9  = sm + 24576;

    const int tid = threadIdx.x, bid = blockIdx.x;
    const int gt = bid * NTHR + tid;
    const int lane = tid & 31;

    // ======== P0: obs gather, out-tail zero, sph split-K (coalesced), tph ==
    for (int i = gt; i < 16384 + 36864; i += NT) {
        if (i < 16384) {
            int m = i >> 13, k = i & 8191;
            int n = k >> 3, d = k & 7;
            g_obs2[i] = obs[n * 96 + d * 12 + 9 + m];
        } else {
            out[12288 + (i - 16384)] = 0.0f;
        }
    }
    if (gt < 24576) {                       // sph: 12 tau x 8 kc x 256 t
        int t = gt & 255;
        int rr = gt >> 8;                   // 0..95
        int tau = rr / 8, kc = rr & 7;
        const float* lr = li + tau * 1024 + kc * 128;
        const float* w  = gs_w1 + (size_t)(kc * 128) * 256 + t;
        float acc = 0.0f;
#pragma unroll 16
        for (int k = 0; k < 128; ++k) acc += lr[k] * w[(size_t)k * 256];
        atomicAdd(&g_sph[tau * 256 + t], acc);
    } else if (gt < 24832) {                // tph
        int t = gt - 24576;
        float acc = 0.0f;
#pragma unroll
        for (int k = 0; k < 36; ++k) acc += tf[k] * gt_w1[k * 256 + t];
        g_tph[t] = acc;                     // bias at read
    }
    grid_barrier(0);

    // ======== P1: u+y (blocks 0..47)  ||  gemv1 (blocks 48..147) ===========
    if (bid < 48) {
        int lw = bid * 16 + (tid >> 5);     // 0..767
        for (int task = lw; task < 3072; task += 768) {
            int n = task / 3, c = task - n * 3;
            int j = n * 12 + 9 + c;
            float wg[8], wt[8], bg[8];
#pragma unroll
            for (int i = 0; i < 8; ++i) {
                int k = lane + 32 * i;
                wg[i] = gs_w2[(size_t)k * 12288 + j];
                wt[i] = gt_w2[(size_t)k * 12288 + j];
                bg[i] = gs_b1[k];
            }
            float tp = 0.0f;
#pragma unroll
            for (int i = 0; i < 8; ++i) {
                int k = lane + 32 * i;
                tp += fmaxf(g_tph[k] + gt_b1[k], 0.0f) * wt[i];
            }
#pragma unroll
            for (int o = 16; o; o >>= 1) tp += __shfl_xor_sync(0xffffffffu, tp, o);
            float tpv = fmaxf(tp + gt_b2[j], 0.0f);
            float bsp = gs_b2[j];

            float bm[12];
            bool doy = (c == 1);
            if (doy && lane < 12) {
#pragma unroll
                for (int q = 0; q < 12; ++q) bm[q] = Bm[lane * 12 + q];
            } else {
#pragma unroll
                for (int q = 0; q < 12; ++q) bm[q] = 0.0f;
            }
            float yacc = 0.0f;
#pragma unroll
            for (int tau = 0; tau < 12; ++tau) {
                float sp = 0.0f;
#pragma unroll
                for (int i = 0; i < 8; ++i)
                    sp += fmaxf(g_sph[tau * 256 + lane + 32 * i] + bg[i], 0.0f) * wg[i];
#pragma unroll
                for (int o = 16; o; o >>= 1) sp += __shfl_xor_sync(0xffffffffu, sp, o);
                float v = fmaxf(sp + bsp, 0.0f) + tpv;
                if (lane == tau) g_U[c * 12288 + n * 12 + tau] = v;
                yacc += bm[tau] * v;
            }
            if (doy && lane < 12) g_Y[n * 12 + lane] = yacc;
        }
    } else {
        int lt = (bid - 48) * NTHR + tid;   // 0..51199
        for (int tile = lt; tile < 512 * 64; tile += 100 * NTHR) {
            int col4 = tile & 511, kc = tile >> 9;
            gemv_tile<8192, 2048, 128, false>(g_obs2, b1, fc_w1, g_s1,
                                              col4 * 4, kc * 128);
        }
    }
    grid_barrier(1);

    // ======== P2: gemv2 (all blocks) =======================================
    for (int tile = gt; tile < 512 * 64; tile += NT) {
        int col4 = tile & 511, kc = tile >> 9;
        gemv_tile<2048, 2048, 32, true>(g_s1, b1, fc_w2, g_s2, col4 * 4, kc * 32);
    }
    grid_barrier(2);

    // ======== P3: gemv3 (all blocks) =======================================
    for (int tile = gt; tile < 3072 * 16; tile += NT) {
        int col4 = tile % 3072, kc = tile / 3072;
        gemv_tile<2048, 12288, 128, true>(g_s2, b2, fc_w3, g_s3, col4 * 4, kc * 128);
    }
    grid_barrier(3);

    // ======== P4: stage Y/X in smem, fused exp-adjacency + SpMM ============
    for (int i = tid; i < 12288 / 4; i += NTHR) {
        ((float4*)sY)[i] = ((const float4*)g_Y)[i];
        float4 bb = ((const float4*)b3)[i % 3072];
        ((float4*)sX10)[i] = relu4b(((const float4*)(g_s3 + 12288))[i], bb);
        ((float4*)sX9)[i]  = relu4b(((const float4*)g_s3)[i], bb);
    }
    __syncthreads();
    {
        int gw = gt >> 5;                   // 0..2367
        for (int task = gw; task < 1536; task += NWARP) {
            int ap = task >> 9;             // 0..2
            int i0 = (task & 511) * 2;      // rows i0, i0+1
            int cidx = (ap == 0) ? 1 : (ap == 1 ? 0 : 2);   // a = 10,9,11
            const float* sX = (ap == 0) ? sX10 : sX9;
            float u0[12], u1[12];
#pragma unroll
            for (int q = 0; q < 12; ++q) {
                u0[q] = g_U[cidx * 12288 + i0 * 12 + q];
                u1[q] = g_U[cidx * 12288 + (i0 + 1) * 12 + q];
            }
            float g0[12], g1[12];
#pragma unroll
            for (int q = 0; q < 12; ++q) { g0[q] = 0.0f; g1[q] = 0.0f; }
            float rs0 = 0.0f, rs1 = 0.0f;
            for (int j = lane; j < 1024; j += 32) {
                const float4* yr = (const float4*)(sY + j * 12);
                float4 ya = yr[0], yb = yr[1], yc = yr[2];
                float s0 = u0[0]*ya.x + u0[1]*ya.y + u0[2] *ya.z + u0[3] *ya.w
                         + u0[4]*yb.x + u0[5]*yb.y + u0[6] *yb.z + u0[7] *yb.w
                         + u0[8]*yc.x + u0[9]*yc.y + u0[10]*yc.z + u0[11]*yc.w;
                float s1 = u1[0]*ya.x + u1[1]*ya.y + u1[2] *ya.z + u1[3] *ya.w
                         + u1[4]*yb.x + u1[5]*yb.y + u1[6] *yb.z + u1[7] *yb.w
                         + u1[8]*yc.x + u1[9]*yc.y + u1[10]*yc.z + u1[11]*yc.w;
                s0 = (s0 >= 0.05f) ? s0 : 0.0f;
                s1 = (s1 >= 0.05f) ? s1 : 0.0f;
                float e0 = __expf(s0), e1 = __expf(s1);
                rs0 += e0; rs1 += e1;
                const float4* xr = (const float4*)(sX + j * 12);
                float4 xa = xr[0], xb = xr[1], xc = xr[2];
                g0[0]+=e0*xa.x; g0[1]+=e0*xa.y; g0[2] +=e0*xa.z; g0[3] +=e0*xa.w;
                g0[4]+=e0*xb.x; g0[5]+=e0*xb.y; g0[6] +=e0*xb.z; g0[7] +=e0*xb.w;
                g0[8]+=e0*xc.x; g0[9]+=e0*xc.y; g0[10]+=e0*xc.z; g0[11]+=e0*xc.w;
                g1[0]+=e1*xa.x; g1[1]+=e1*xa.y; g1[2] +=e1*xa.z; g1[3] +=e1*xa.w;
                g1[4]+=e1*xb.x; g1[5]+=e1*xb.y; g1[6] +=e1*xb.z; g1[7] +=e1*xb.w;
                g1[8]+=e1*xc.x; g1[9]+=e1*xc.y; g1[10]+=e1*xc.z; g1[11]+=e1*xc.w;
            }
#pragma unroll
            for (int o = 16; o; o >>= 1) {
                rs0 += __shfl_xor_sync(0xffffffffu, rs0, o);
                rs1 += __shfl_xor_sync(0xffffffffu, rs1, o);
#pragma unroll
                for (int q = 0; q < 12; ++q) {
                    g0[q] += __shfl_xor_sync(0xffffffffu, g0[q], o);
                    g1[q] += __shfl_xor_sync(0xffffffffu, g1[q], o);
                }
            }
            if (lane == 0) {
                float inv0 = 1.0f / rs0, inv1 = 1.0f / rs1;
                float* G0 = g_G + (ap * 1024 + i0) * 12;
#pragma unroll
                for (int q = 0; q < 12; ++q) {
                    G0[q]      = g0[q] * inv0;
                    G0[12 + q] = g1[q] * inv1;
                }
            }
        }
    }
    grid_barrier(4);

    // ======== P5: combine + zero accumulators ==============================
    for (int idx = gt; idx < 12288 + 35840; idx += NT) {
        if (idx < 12288) {
            int n = idx / 12, f = idx % 12;
            float acc1 = bvec[f], acc2 = bvec[f];
#pragma unroll
            for (int q = 0; q < 12; ++q) {
                acc1 += g_G[n * 12 + q] * (Wf[q * 12 + f] + Wb[q * 12 + f]);
                acc2 += g_G[(1024 + n) * 12 + q] * Wf[144 + q * 12 + f]
                      + g_G[(2048 + n) * 12 + q] * Wb[144 + q * 12 + f];
            }
            out[idx] = fmaxf(acc1, 0.0f) + fmaxf(acc2, 0.0f);
        } else {
            int i = idx - 12288;
            if (i < 4096)        g_s1[i] = 0.0f;
            else if (i < 8192)   g_s2[i - 4096] = 0.0f;
            else if (i < 32768)  g_s3[i - 8192] = 0.0f;
            else                 g_sph[i - 32768] = 0.0f;
        }
    }
}

// ---------------- launch ----------------
extern "C" void kernel_launch(void* const* d_in, const int* in_sizes, int n_in,
                              void* d_out, int out_size) {
    const float* obs    = (const float*)d_in[0];
    const float* tf     = (const float*)d_in[1];
    const float* fc_w1  = (const float*)d_in[2];
    const float* fc_b1  = (const float*)d_in[3];
    const float* fc_w2  = (const float*)d_in[4];
    const float* fc_b2  = (const float*)d_in[5];
    const float* fc_w3  = (const float*)d_in[6];
    const float* fc_b3  = (const float*)d_in[7];
    const float* Wf     = (const float*)d_in[8];
    const float* Wb     = (const float*)d_in[9];
    const float* bvec   = (const float*)d_in[10];
    const float* li     = (const float*)d_in[11];
    const float* gs_w1  = (const float*)d_in[12];
    const float* gs_b1  = (const float*)d_in[13];
    const float* gs_w2  = (const float*)d_in[14];
    const float* gs_b2  = (const float*)d_in[15];
    const float* gt_w1  = (const float*)d_in[16];
    const float* gt_b1  = (const float*)d_in[17];
    const float* gt_w2  = (const float*)d_in[18];
    const float* gt_b2  = (const float*)d_in[19];
    const float* Bm     = (const float*)d_in[20];
    float* out = (float*)d_out;

    cudaFuncSetAttribute(mega3_kernel,
                         cudaFuncAttributeMaxDynamicSharedMemorySize,
                         SMEM_FLOATS * sizeof(float));

    mega3_kernel<<<NBLK, NTHR, SMEM_FLOATS * sizeof(float)>>>(
        obs, tf, fc_w1, fc_b1, fc_w2, fc_b2, fc_w3, fc_b3,
        Wf, Wb, bvec, li, gs_w1, gs_b1, gs_w2, gs_b2,
        gt_w1, gt_b1, gt_w2, gt_b2, Bm, out);
}